// round 1
// baseline (speedup 1.0000x reference)
#include <cuda_runtime.h>
#include <cstdint>

// Problem constants: q,k,v are [B=4, H=16, S=2048, D=64] fp32.
// Output buffer layout (tuple flatten): out [B,H,S,D] then attn [B,H,S,S].
#define BATCH 4
#define HEADS 16
#define SEQ   2048
#define HDIM  64
#define NBH   (BATCH*HEADS)

#define TQ   16            // q rows per CTA
#define TK   256           // key/value tile
#define SST  2052          // padded smem score row stride (words), 2052%32=4
#define NTHREADS 256

// fold 1/temperature (1/8) and log2(e) into the Q scale so softmax runs in exp2 domain
#define QSCALE (1.4426950408889634f / 8.0f)

// K transposed to [bh][d][s] so QK^T smem tiles load conflict-free (33.5 MB scratch)
__device__ float g_kt[(size_t)NBH * HDIM * SEQ];

// ---------------------------------------------------------------------------
// Kernel 1: global transpose K[bh][s][d] -> g_kt[bh][d][s]
// ---------------------------------------------------------------------------
__global__ void transpose_k_kernel(const float* __restrict__ k) {
    __shared__ float t[32][33];
    int bh = blockIdx.z;
    int s0 = blockIdx.x * 32;
    int d0 = blockIdx.y * 32;
    const float* kb = k + (size_t)bh * SEQ * HDIM;
    float* ktb = g_kt + (size_t)bh * HDIM * SEQ;
    int tx = threadIdx.x, ty = threadIdx.y;
#pragma unroll
    for (int i = 0; i < 32; i += 8)
        t[ty + i][tx] = kb[(size_t)(s0 + ty + i) * HDIM + d0 + tx];
    __syncthreads();
#pragma unroll
    for (int i = 0; i < 32; i += 8)
        ktb[(size_t)(d0 + ty + i) * SEQ + s0 + tx] = t[tx][ty + i];
}

// ---------------------------------------------------------------------------
// Fast exp2 on the FMA pipe (no MUFU). |rel err| < 3e-6 on f in [-0.5, 0.5].
// ---------------------------------------------------------------------------
__device__ __forceinline__ float fast_exp2(float y) {
    y = fmaxf(y, -120.0f);
    float r  = y + 12582912.0f;        // round-to-nearest-int via magic add
    float fi = r - 12582912.0f;
    float f  = y - fi;                 // f in [-0.5, 0.5]
    float p  = 1.3333558146428443e-3f;
    p = fmaf(p, f, 9.6181291076284772e-3f);
    p = fmaf(p, f, 5.5504108664821580e-2f);
    p = fmaf(p, f, 2.4022650695910072e-1f);
    p = fmaf(p, f, 6.9314718055994531e-1f);
    p = fmaf(p, f, 1.0f);
    int e = (int)fi;                   // e in [-120, ~+8]
    return __int_as_float(__float_as_int(p) + (e << 23));
}

// ---------------------------------------------------------------------------
// Kernel 2: fused attention for one (bh, 16-q-row) tile.
// smem: Qs[16*64] | invs[16] | tile[256*64] (K^T then V) | scores[16*2052]
// ---------------------------------------------------------------------------
__global__ __launch_bounds__(NTHREADS, 1)
void attn_kernel(const float* __restrict__ q,
                 const float* __restrict__ v,
                 float* __restrict__ out,
                 float* __restrict__ attn) {
    extern __shared__ float sm[];
    float* Qs   = sm;                    // 1024
    float* invs = Qs + TQ * HDIM;        // 16
    float* tile = invs + 16;             // 16384
    float* sc   = tile + TK * HDIM;      // 16*2052

    const int bh  = blockIdx.y;
    const int q0  = blockIdx.x * TQ;
    const int tid = threadIdx.x;

    // ---- load Q tile, pre-scaled (1024 floats = 256 float4) ----
    {
        const float4* qg = (const float4*)(q + ((size_t)bh * SEQ + q0) * HDIM);
        float4 t = qg[tid];
        t.x *= QSCALE; t.y *= QSCALE; t.z *= QSCALE; t.w *= QSCALE;
        ((float4*)Qs)[tid] = t;
    }
    __syncthreads();

    // ================= Phase 1: scores = Qs @ K^T =================
    {
        const int rc = tid >> 5;          // 0..7 -> rows {2rc, 2rc+1}
        const int c  = tid & 31;          // key group: cols {4c+i} u {128+4c+i}
        const int r0 = 2 * rc;
        const float* ktg = g_kt + (size_t)bh * HDIM * SEQ;
        const float* qr0 = Qs + r0 * HDIM;
        const float* qr1 = Qs + (r0 + 1) * HDIM;

        for (int kt = 0; kt < SEQ; kt += TK) {
            // load K^T tile [64][256], fully coalesced + conflict-free
            for (int i = tid; i < (TK * HDIM) / 4; i += NTHREADS) {
                int d = i >> 6, c4 = i & 63;
                *(float4*)(tile + d * TK + 4 * c4) =
                    *(const float4*)(ktg + (size_t)d * SEQ + kt + 4 * c4);
            }
            __syncthreads();

            float a0[8], a1[8];
#pragma unroll
            for (int j = 0; j < 8; j++) { a0[j] = 0.f; a1[j] = 0.f; }

#pragma unroll 8
            for (int d = 0; d < HDIM; d++) {
                float4 ka = *(const float4*)(tile + d * TK + 4 * c);
                float4 kb = *(const float4*)(tile + d * TK + (TK / 2) + 4 * c);
                float qa = qr0[d], qb = qr1[d];
                a0[0] = fmaf(qa, ka.x, a0[0]); a0[1] = fmaf(qa, ka.y, a0[1]);
                a0[2] = fmaf(qa, ka.z, a0[2]); a0[3] = fmaf(qa, ka.w, a0[3]);
                a0[4] = fmaf(qa, kb.x, a0[4]); a0[5] = fmaf(qa, kb.y, a0[5]);
                a0[6] = fmaf(qa, kb.z, a0[6]); a0[7] = fmaf(qa, kb.w, a0[7]);
                a1[0] = fmaf(qb, ka.x, a1[0]); a1[1] = fmaf(qb, ka.y, a1[1]);
                a1[2] = fmaf(qb, ka.z, a1[2]); a1[3] = fmaf(qb, ka.w, a1[3]);
                a1[4] = fmaf(qb, kb.x, a1[4]); a1[5] = fmaf(qb, kb.y, a1[5]);
                a1[6] = fmaf(qb, kb.z, a1[6]); a1[7] = fmaf(qb, kb.w, a1[7]);
            }
            *(float4*)(sc + (size_t)r0 * SST + kt + 4 * c)            = make_float4(a0[0], a0[1], a0[2], a0[3]);
            *(float4*)(sc + (size_t)r0 * SST + kt + 128 + 4 * c)      = make_float4(a0[4], a0[5], a0[6], a0[7]);
            *(float4*)(sc + (size_t)(r0 + 1) * SST + kt + 4 * c)      = make_float4(a1[0], a1[1], a1[2], a1[3]);
            *(float4*)(sc + (size_t)(r0 + 1) * SST + kt + 128 + 4 * c)= make_float4(a1[4], a1[5], a1[6], a1[7]);
            __syncthreads();
        }
    }

    // ================= Phase 2: softmax (exp2 domain) + attn writeout =======
    {
        const int row = tid >> 4;         // 0..15
        const int l   = tid & 15;
        float* srow = sc + (size_t)row * SST;
        float4* srow4 = (float4*)srow;

        float m = -1e30f;
        for (int j = l; j < SEQ / 4; j += 16) {
            float4 t = srow4[j];
            m = fmaxf(m, fmaxf(fmaxf(t.x, t.y), fmaxf(t.z, t.w)));
        }
#pragma unroll
        for (int o = 8; o >= 1; o >>= 1) m = fmaxf(m, __shfl_xor_sync(0xffffffffu, m, o));

        float sum = 0.f;
        for (int j = l; j < SEQ / 4; j += 16) {
            float4 t = srow4[j];
            t.x = fast_exp2(t.x - m); t.y = fast_exp2(t.y - m);
            t.z = fast_exp2(t.z - m); t.w = fast_exp2(t.w - m);
            srow4[j] = t;                         // keep UNNORMALIZED for PV
            sum += (t.x + t.y) + (t.z + t.w);
        }
#pragma unroll
        for (int o = 8; o >= 1; o >>= 1) sum += __shfl_xor_sync(0xffffffffu, sum, o);
        float inv = 1.0f / sum;
        if (l == 0) invs[row] = inv;

        // normalized attn to gmem (coalesced float4)
        float4* ag = (float4*)(attn + ((size_t)bh * SEQ + q0 + row) * SEQ);
        for (int j = l; j < SEQ / 4; j += 16) {
            float4 t = srow4[j];
            t.x *= inv; t.y *= inv; t.z *= inv; t.w *= inv;
            ag[j] = t;
        }
    }
    __syncthreads();

    // ================= Phase 3: out = (P @ V) * inv ========================
    {
        const int ks  = tid >> 6;          // 0..3 : k-split
        const int rc2 = (tid >> 3) & 7;    // rows {2rc2, 2rc2+1}
        const int c8  = tid & 7;           // cols {4c8+i} u {32+4c8+i}
        const float* vbase = v + (size_t)bh * SEQ * HDIM;

        float o0[8], o1[8];
#pragma unroll
        for (int j = 0; j < 8; j++) { o0[j] = 0.f; o1[j] = 0.f; }

        for (int kt = 0; kt < SEQ; kt += TK) {
            // load V tile [256][64], coalesced
            for (int i = tid; i < (TK * HDIM) / 4; i += NTHREADS) {
                int kk = i >> 4, c4 = i & 15;
                *(float4*)(tile + kk * HDIM + 4 * c4) =
                    *(const float4*)(vbase + (size_t)(kt + kk) * HDIM + 4 * c4);
            }
            __syncthreads();

            const float* p0row = sc + (size_t)(2 * rc2) * SST + kt;
            const float* p1row = sc + (size_t)(2 * rc2 + 1) * SST + kt;
#pragma unroll 4
            for (int kk = 0; kk < TK / 4; kk++) {
                int k = ks * (TK / 4) + kk;
                float4 va = *(const float4*)(tile + k * HDIM + 4 * c8);
                float4 vb = *(const float4*)(tile + k * HDIM + 32 + 4 * c8);
                float p0 = p0row[k];
                float p1 = p1row[k];
                o0[0] = fmaf(p0, va.x, o0[0]); o0[1] = fmaf(p0, va.y, o0[1]);
                o0[2] = fmaf(p0, va.z, o0[2]); o0[3] = fmaf(p0, va.w, o0[3]);
                o0[4] = fmaf(p0, vb.x, o0[4]); o0[5] = fmaf(p0, vb.y, o0[5]);
                o0[6] = fmaf(p0, vb.z, o0[6]); o0[7] = fmaf(p0, vb.w, o0[7]);
                o1[0] = fmaf(p1, va.x, o1[0]); o1[1] = fmaf(p1, va.y, o1[1]);
                o1[2] = fmaf(p1, va.z, o1[2]); o1[3] = fmaf(p1, va.w, o1[3]);
                o1[4] = fmaf(p1, vb.x, o1[4]); o1[5] = fmaf(p1, vb.y, o1[5]);
                o1[6] = fmaf(p1, vb.z, o1[6]); o1[7] = fmaf(p1, vb.w, o1[7]);
            }
            __syncthreads();
        }

        // stage partials for k-split reduction (reuse tile buffer: 256*16 floats)
#pragma unroll
        for (int i = 0; i < 8; i++) {
            tile[tid + NTHREADS * i]       = o0[i];
            tile[tid + NTHREADS * (i + 8)] = o1[i];
        }
        __syncthreads();

        if (ks == 0) {  // tids 0..63 finish 16 outputs each
            float invA = invs[2 * rc2];
            float invB = invs[2 * rc2 + 1];
            float* ob = out + ((size_t)bh * SEQ + q0) * HDIM;
#pragma unroll
            for (int i = 0; i < 16; i++) {
                float s = tile[tid + NTHREADS * i]
                        + tile[tid + 64 + NTHREADS * i]
                        + tile[tid + 128 + NTHREADS * i]
                        + tile[tid + 192 + NTHREADS * i];
                int a = i >> 3;            // 0: row 2rc2, 1: row 2rc2+1
                int b = i & 7;
                int col = 4 * c8 + (b & 3) + ((b & 4) ? 32 : 0);
                int rr = 2 * rc2 + a;
                ob[(size_t)rr * HDIM + col] = s * (a ? invB : invA);
            }
        }
    }
}

// ---------------------------------------------------------------------------
extern "C" void kernel_launch(void* const* d_in, const int* in_sizes, int n_in,
                              void* d_out, int out_size) {
    const float* q = (const float*)d_in[0];
    const float* k = (const float*)d_in[1];
    const float* v = (const float*)d_in[2];
    float* out  = (float*)d_out;
    float* attn = out + (size_t)NBH * SEQ * HDIM;

    // K transpose into __device__ scratch
    dim3 tg(SEQ / 32, HDIM / 32, NBH);
    dim3 tb(32, 8);
    transpose_k_kernel<<<tg, tb>>>(k);

    const int smem_bytes = (TQ * HDIM + 16 + TK * HDIM + TQ * SST) * (int)sizeof(float);
    cudaFuncSetAttribute(attn_kernel, cudaFuncAttributeMaxDynamicSharedMemorySize, smem_bytes);

    dim3 grid(SEQ / TQ, NBH);
    attn_kernel<<<grid, NTHREADS, smem_bytes>>>(q, v, out, attn);
}

// round 5
// speedup vs baseline: 2.6829x; 2.6829x over previous
#include <cuda_runtime.h>
#include <cuda_bf16.h>
#include <cstdint>

// q,k,v: [B=4,H=16,S=2048,D=64] fp32. out = [B,H,S,D] then attn [B,H,S,S] (fp32).
#define SEQ   2048
#define HDIM  64
#define NBH   64
#define QTILE 128
#define TKEY  128
#define NTILES (SEQ/TKEY)
#define NTHREADS 256

// fold 1/temperature (1/8) and log2(e) into Q: softmax runs in exp2 domain
#define QSCALE (1.4426950408889634f / 8.0f)

__device__ float g_vt[(size_t)NBH * HDIM * SEQ];   // V^T [bh][d][s]
__device__ float g_inv[(size_t)NBH * SEQ];         // per-row 1/sum

// ---------------------------------------------------------------------------
__device__ __forceinline__ uint32_t smem_u32(const void* p) {
    uint32_t a;
    asm("{ .reg .u64 t; cvta.to.shared.u64 t, %1; cvt.u32.u64 %0, t; }" : "=r"(a) : "l"(p));
    return a;
}
__device__ __forceinline__ void ldm4(uint32_t* r, uint32_t a) {
    asm volatile("ldmatrix.sync.aligned.m8n8.x4.shared.b16 {%0,%1,%2,%3}, [%4];"
                 : "=r"(r[0]), "=r"(r[1]), "=r"(r[2]), "=r"(r[3]) : "r"(a));
}
__device__ __forceinline__ void mma16816(float* c, const uint32_t* a, const uint32_t* b) {
    asm volatile("mma.sync.aligned.m16n8k16.row.col.f32.bf16.bf16.f32 "
                 "{%0,%1,%2,%3},{%4,%5,%6,%7},{%8,%9},{%0,%1,%2,%3};"
                 : "+f"(c[0]), "+f"(c[1]), "+f"(c[2]), "+f"(c[3])
                 : "r"(a[0]), "r"(a[1]), "r"(a[2]), "r"(a[3]), "r"(b[0]), "r"(b[1]));
}
// split pair (a,b) into packed bf16x2 hi + residual lo
__device__ __forceinline__ void split2(float a, float b, uint32_t& h, uint32_t& l) {
    __nv_bfloat16 ha = __float2bfloat16_rn(a), hb = __float2bfloat16_rn(b);
    float ra = a - __bfloat162float(ha), rb = b - __bfloat162float(hb);
    __nv_bfloat162 H(ha, hb);
    __nv_bfloat162 L = __floats2bfloat162_rn(ra, rb);
    h = *reinterpret_cast<uint32_t*>(&H);
    l = *reinterpret_cast<uint32_t*>(&L);
}
__device__ __forceinline__ float fast_exp2(float y) {
    y = fmaxf(y, -120.0f);
    float r  = y + 12582912.0f;
    float fi = r - 12582912.0f;
    float f  = y - fi;
    float p  = 1.3333558146428443e-3f;
    p = fmaf(p, f, 9.6181291076284772e-3f);
    p = fmaf(p, f, 5.5504108664821580e-2f);
    p = fmaf(p, f, 2.4022650695910072e-1f);
    p = fmaf(p, f, 6.9314718055994531e-1f);
    p = fmaf(p, f, 1.0f);
    int e = (int)fi;
    return __int_as_float(__float_as_int(p) + (e << 23));
}

// load [128 rows][64 f32] (row stride 64) -> bf16 hi/lo smem, 128B rows, XOR swizzle
__device__ __forceinline__ void load_tile_rc(const float* __restrict__ src, char* hi, char* lo,
                                             int tid, float scale) {
#pragma unroll
    for (int i = tid; i < 1024; i += NTHREADS) {
        int row = i >> 3, c = i & 7;
        const float4* s = (const float4*)(src + row * 64 + c * 8);
        float4 f0 = s[0], f1 = s[1];
        f0.x *= scale; f0.y *= scale; f0.z *= scale; f0.w *= scale;
        f1.x *= scale; f1.y *= scale; f1.z *= scale; f1.w *= scale;
        uint32_t h0, l0, h1, l1, h2, l2, h3, l3;
        split2(f0.x, f0.y, h0, l0); split2(f0.z, f0.w, h1, l1);
        split2(f1.x, f1.y, h2, l2); split2(f1.z, f1.w, h3, l3);
        uint32_t off = row * 128 + ((c ^ (row & 7)) * 16);
        *(uint4*)(hi + off) = make_uint4(h0, h1, h2, h3);
        *(uint4*)(lo + off) = make_uint4(l0, l1, l2, l3);
    }
}
// load V^T tile [64 d][128 keys] f32 (row stride SEQ) -> bf16 hi/lo, 256B rows, swizzle
__device__ __forceinline__ void load_tile_vt(const float* __restrict__ src, char* hi, char* lo,
                                             int tid) {
#pragma unroll
    for (int i = tid; i < 1024; i += NTHREADS) {
        int d = i >> 4, c = i & 15;
        const float4* s = (const float4*)(src + (size_t)d * SEQ + c * 8);
        float4 f0 = s[0], f1 = s[1];
        uint32_t h0, l0, h1, l1, h2, l2, h3, l3;
        split2(f0.x, f0.y, h0, l0); split2(f0.z, f0.w, h1, l1);
        split2(f1.x, f1.y, h2, l2); split2(f1.z, f1.w, h3, l3);
        uint32_t off = d * 256 + ((c ^ (d & 7)) * 16);
        *(uint4*)(hi + off) = make_uint4(h0, h1, h2, h3);
        *(uint4*)(lo + off) = make_uint4(l0, l1, l2, l3);
    }
}

// Q fragment loads: A frags for rows 16w..16w+15, 4 k-steps
__device__ __forceinline__ void load_q_frags(uint32_t qf[4][4], uint32_t base, int w, int lane) {
#pragma unroll
    for (int kb = 0; kb < 4; kb++) {
        int row = 16 * w + (lane & 15);
        int ch = (2 * kb + (lane >> 4)) ^ (row & 7);
        ldm4(qf[kb], base + row * 128 + ch * 16);
    }
}

// QK^T for one 128-key tile: s[16][4] += (Qh+Ql)(Kh+Kl) triple product
__device__ __forceinline__ void qk_tile(float s[16][4], const uint32_t qh[4][4],
                                        const uint32_t ql[4][4], uint32_t khb, uint32_t klb,
                                        int lane) {
    const int rowk = (lane & 7);
    const int m = lane >> 3;
#pragma unroll
    for (int nb = 0; nb < 16; nb++) {
        int row = 8 * nb + rowk;
        uint32_t a1 = row * 128 + ((m ^ (row & 7)) * 16);
        uint32_t a2 = row * 128 + (((4 + m) ^ (row & 7)) * 16);
        uint32_t kh[8], kl[8];
        ldm4(kh, khb + a1); ldm4(kh + 4, khb + a2);
        ldm4(kl, klb + a1); ldm4(kl + 4, klb + a2);
#pragma unroll
        for (int kb = 0; kb < 4; kb++) {
            mma16816(s[nb], qh[kb], kh + 2 * kb);
            mma16816(s[nb], qh[kb], kl + 2 * kb);
            mma16816(s[nb], ql[kb], kh + 2 * kb);
        }
    }
}

// ---------------------------------------------------------------------------
// V transpose: v[bh][s][d] -> g_vt[bh][d][s]
__global__ void transpose_v_kernel(const float* __restrict__ v) {
    __shared__ float t[32][33];
    int bh = blockIdx.z, s0 = blockIdx.x * 32, d0 = blockIdx.y * 32;
    const float* vb = v + (size_t)bh * SEQ * HDIM;
    float* vtb = g_vt + (size_t)bh * HDIM * SEQ;
    int tx = threadIdx.x, ty = threadIdx.y;
#pragma unroll
    for (int i = 0; i < 32; i += 8)
        t[ty + i][tx] = vb[(size_t)(s0 + ty + i) * HDIM + d0 + tx];
    __syncthreads();
#pragma unroll
    for (int i = 0; i < 32; i += 8)
        vtb[(size_t)(d0 + ty + i) * SEQ + s0 + tx] = t[tx][ty + i];
}

// ---------------------------------------------------------------------------
// Pass A: row sums only -> g_inv
__global__ __launch_bounds__(NTHREADS, 1)
void attn_sum_kernel(const float* __restrict__ q, const float* __restrict__ k) {
    extern __shared__ char sm[];
    char *QHI = sm, *QLO = sm + 16384, *KHI = sm + 32768, *KLO = sm + 49152;
    const int tid = threadIdx.x, lane = tid & 31, w = tid >> 5;
    const int bh = blockIdx.y, q0 = blockIdx.x * QTILE;

    load_tile_rc(q + ((size_t)bh * SEQ + q0) * HDIM, QHI, QLO, tid, QSCALE);
    __syncthreads();

    uint32_t qh[4][4], ql[4][4];
    load_q_frags(qh, smem_u32(QHI), w, lane);
    load_q_frags(ql, smem_u32(QLO), w, lane);
    const uint32_t khb = smem_u32(KHI), klb = smem_u32(KLO);
    const float* kg = k + (size_t)bh * SEQ * HDIM;

    float sum0 = 0.f, sum1 = 0.f;
    for (int kt = 0; kt < NTILES; kt++) {
        __syncthreads();
        load_tile_rc(kg + (size_t)kt * TKEY * HDIM, KHI, KLO, tid, 1.0f);
        __syncthreads();
        float s[16][4];
#pragma unroll
        for (int nb = 0; nb < 16; nb++) { s[nb][0] = s[nb][1] = s[nb][2] = s[nb][3] = 0.f; }
        qk_tile(s, qh, ql, khb, klb, lane);
#pragma unroll
        for (int nb = 0; nb < 16; nb++) {
            sum0 += fast_exp2(s[nb][0]) + fast_exp2(s[nb][1]);
            sum1 += fast_exp2(s[nb][2]) + fast_exp2(s[nb][3]);
        }
    }
    sum0 += __shfl_xor_sync(0xffffffffu, sum0, 1);
    sum0 += __shfl_xor_sync(0xffffffffu, sum0, 2);
    sum1 += __shfl_xor_sync(0xffffffffu, sum1, 1);
    sum1 += __shfl_xor_sync(0xffffffffu, sum1, 2);
    if ((lane & 3) == 0) {
        size_t base = (size_t)bh * SEQ + q0 + 16 * w + (lane >> 2);
        g_inv[base] = 1.0f / sum0;
        g_inv[base + 8] = 1.0f / sum1;
    }
}

// ---------------------------------------------------------------------------
// Pass B: recompute scores, normalize, write attn, PV -> out
__global__ __launch_bounds__(NTHREADS, 1)
void attn_main_kernel(const float* __restrict__ q, const float* __restrict__ k,
                      float* __restrict__ out, float* __restrict__ attn) {
    extern __shared__ char sm[];
    char *QHI = sm, *QLO = sm + 16384, *KHI = sm + 32768, *KLO = sm + 49152;
    char *VHI = sm + 65536, *VLO = sm + 81920;
    const int tid = threadIdx.x, lane = tid & 31, w = tid >> 5;
    const int bh = blockIdx.y, q0 = blockIdx.x * QTILE;

    load_tile_rc(q + ((size_t)bh * SEQ + q0) * HDIM, QHI, QLO, tid, QSCALE);
    __syncthreads();

    uint32_t qh[4][4], ql[4][4];
    load_q_frags(qh, smem_u32(QHI), w, lane);
    load_q_frags(ql, smem_u32(QLO), w, lane);
    const uint32_t khb = smem_u32(KHI), klb = smem_u32(KLO);
    const uint32_t vhb = smem_u32(VHI), vlb = smem_u32(VLO);
    const float* kg  = k + (size_t)bh * SEQ * HDIM;
    const float* vtg = g_vt + (size_t)bh * HDIM * SEQ;

    const int r = lane >> 2;
    const float inv0 = g_inv[(size_t)bh * SEQ + q0 + 16 * w + r];
    const float inv1 = g_inv[(size_t)bh * SEQ + q0 + 16 * w + r + 8];
    float* arow0 = attn + ((size_t)bh * SEQ + q0 + 16 * w + r) * SEQ + 2 * (lane & 3);
    float* arow1 = arow0 + (size_t)8 * SEQ;

    float o[8][4];
#pragma unroll
    for (int nb = 0; nb < 8; nb++) { o[nb][0] = o[nb][1] = o[nb][2] = o[nb][3] = 0.f; }

    for (int kt = 0; kt < NTILES; kt++) {
        __syncthreads();
        load_tile_rc(kg + (size_t)kt * TKEY * HDIM, KHI, KLO, tid, 1.0f);
        load_tile_vt(vtg + (size_t)kt * TKEY, VHI, VLO, tid);
        __syncthreads();

        float s[16][4];
#pragma unroll
        for (int nb = 0; nb < 16; nb++) { s[nb][0] = s[nb][1] = s[nb][2] = s[nb][3] = 0.f; }
        qk_tile(s, qh, ql, khb, klb, lane);

        // exp2 -> normalize -> write attn -> pack P frags (hi/lo)
        uint32_t phA[16], phB[16], plA[16], plB[16];
#pragma unroll
        for (int nb = 0; nb < 16; nb++) {
            float p0 = fast_exp2(s[nb][0]) * inv0;
            float p1 = fast_exp2(s[nb][1]) * inv0;
            float p2 = fast_exp2(s[nb][2]) * inv1;
            float p3 = fast_exp2(s[nb][3]) * inv1;
            *(float2*)(arow0 + kt * TKEY + nb * 8) = make_float2(p0, p1);
            *(float2*)(arow1 + kt * TKEY + nb * 8) = make_float2(p2, p3);
            split2(p0, p1, phA[nb], plA[nb]);
            split2(p2, p3, phB[nb], plB[nb]);
        }

        // PV: O += (Ph+Pl)(Vh+Vl) triple product
        const int rowm = lane & 7;
        const int m = lane >> 3;
#pragma unroll
        for (int nb2 = 0; nb2 < 8; nb2++) {
            int row = 8 * nb2 + rowm;
            uint32_t vh[16], vl[16];
#pragma unroll
            for (int qd = 0; qd < 4; qd++) {
                uint32_t a = row * 256 + (((4 * qd + m) ^ (row & 7)) * 16);
                ldm4(vh + 4 * qd, vhb + a);
                ldm4(vl + 4 * qd, vlb + a);
            }
#pragma unroll
            for (int kb = 0; kb < 8; kb++) {
                uint32_t ah[4] = {phA[2 * kb], phB[2 * kb], phA[2 * kb + 1], phB[2 * kb + 1]};
                uint32_t al[4] = {plA[2 * kb], plB[2 * kb], plA[2 * kb + 1], plB[2 * kb + 1]};
                mma16816(o[nb2], ah, vh + 2 * kb);
                mma16816(o[nb2], ah, vl + 2 * kb);
                mma16816(o[nb2], al, vh + 2 * kb);
            }
        }
    }

    // write O (already normalized)
    float* orow0 = out + ((size_t)bh * SEQ + q0 + 16 * w + r) * HDIM + 2 * (lane & 3);
    float* orow1 = orow0 + 8 * HDIM;
#pragma unroll
    for (int nb2 = 0; nb2 < 8; nb2++) {
        *(float2*)(orow0 + nb2 * 8) = make_float2(o[nb2][0], o[nb2][1]);
        *(float2*)(orow1 + nb2 * 8) = make_float2(o[nb2][2], o[nb2][3]);
    }
}

// ---------------------------------------------------------------------------
extern "C" void kernel_launch(void* const* d_in, const int* in_sizes, int n_in,
                              void* d_out, int out_size) {
    const float* q = (const float*)d_in[0];
    const float* k = (const float*)d_in[1];
    const float* v = (const float*)d_in[2];
    float* out  = (float*)d_out;
    float* attn = out + (size_t)NBH * SEQ * HDIM;

    dim3 tg(SEQ / 32, HDIM / 32, NBH);
    transpose_v_kernel<<<tg, dim3(32, 8)>>>(v);

    const int smA = 65536, smB = 98304;
    cudaFuncSetAttribute(attn_sum_kernel, cudaFuncAttributeMaxDynamicSharedMemorySize, smA);
    cudaFuncSetAttribute(attn_main_kernel, cudaFuncAttributeMaxDynamicSharedMemorySize, smB);

    dim3 grid(SEQ / QTILE, NBH);
    attn_sum_kernel<<<grid, NTHREADS, smA>>>(q, k);
    attn_main_kernel<<<grid, NTHREADS, smB>>>(q, k, out, attn);
}